// round 10
// baseline (speedup 1.0000x reference)
#include <cuda_runtime.h>
#include <cuda_bf16.h>
#include <stdint.h>
#include <math.h>

#define CIN   64
#define COUT  128
#define HIN   256
#define WIN   256
#define NP    4096
#define BATCH 4
#define KDIM  1024

// bf16 hi/lo splits: Q, K, V all stored [b][n][o] (row = token, col = channel)
__device__ __align__(128) __nv_bfloat16 gQh[BATCH][NP][COUT];
__device__ __align__(128) __nv_bfloat16 gQl[BATCH][NP][COUT];
__device__ __align__(128) __nv_bfloat16 gKh[BATCH][NP][COUT];
__device__ __align__(128) __nv_bfloat16 gKl[BATCH][NP][COUT];
__device__ __align__(128) __nv_bfloat16 gVh[BATCH][NP][COUT];
__device__ __align__(128) __nv_bfloat16 gVl[BATCH][NP][COUT];
// im2col activations [b][n][ck] and split weights [mat][o][ck]
__device__ __align__(128) __nv_bfloat16 gAh[BATCH][NP][KDIM];
__device__ __align__(128) __nv_bfloat16 gAl[BATCH][NP][KDIM];
__device__ __align__(128) __nv_bfloat16 gWh[3][COUT][KDIM];
__device__ __align__(128) __nv_bfloat16 gWl[3][COUT][KDIM];

// ---------------------------------------------------------------------------
// helpers
// ---------------------------------------------------------------------------
__device__ __forceinline__ uint32_t smem_u32(const void* p) {
    uint32_t a;
    asm("{ .reg .u64 t; cvta.to.shared.u64 t, %1; cvt.u32.u64 %0, t; }" : "=r"(a) : "l"(p));
    return a;
}
__device__ __forceinline__ void ldsm4(uint32_t r[4], uint32_t addr) {
    asm volatile("ldmatrix.sync.aligned.m8n8.x4.shared.b16 {%0,%1,%2,%3}, [%4];"
                 : "=r"(r[0]), "=r"(r[1]), "=r"(r[2]), "=r"(r[3]) : "r"(addr));
}
__device__ __forceinline__ void ldsm4t(uint32_t r[4], uint32_t addr) {
    asm volatile("ldmatrix.sync.aligned.m8n8.x4.trans.shared.b16 {%0,%1,%2,%3}, [%4];"
                 : "=r"(r[0]), "=r"(r[1]), "=r"(r[2]), "=r"(r[3]) : "r"(addr));
}
__device__ __forceinline__ void mma_bf16(float d[4], const uint32_t a[4],
                                         uint32_t b0, uint32_t b1) {
    asm volatile("mma.sync.aligned.m16n8k16.row.col.f32.bf16.bf16.f32 "
                 "{%0,%1,%2,%3}, {%4,%5,%6,%7}, {%8,%9}, {%0,%1,%2,%3};"
                 : "+f"(d[0]), "+f"(d[1]), "+f"(d[2]), "+f"(d[3])
                 : "r"(a[0]), "r"(a[1]), "r"(a[2]), "r"(a[3]), "r"(b0), "r"(b1));
}
__device__ __forceinline__ void cpasync16(uint32_t dst, const void* src) {
    asm volatile("cp.async.cg.shared.global [%0], [%1], 16;" :: "r"(dst), "l"(src));
}
#define CP_COMMIT() asm volatile("cp.async.commit_group;" ::: "memory")
#define CP_WAIT1()  asm volatile("cp.async.wait_group 1;" ::: "memory")
#define CP_WAIT0()  asm volatile("cp.async.wait_group 0;" ::: "memory")

__device__ __forceinline__ uint32_t pack_bf2(__nv_bfloat16 a, __nv_bfloat16 b) {
    return ((uint32_t)__bfloat16_as_ushort(b) << 16) | (uint32_t)__bfloat16_as_ushort(a);
}
__device__ __forceinline__ void split2(float x, float y, uint32_t& h, uint32_t& l) {
    __nv_bfloat16 hx = __float2bfloat16(x), hy = __float2bfloat16(y);
    h = pack_bf2(hx, hy);
    l = pack_bf2(__float2bfloat16(x - __bfloat162float(hx)),
                 __float2bfloat16(y - __bfloat162float(hy)));
}

// ---------------------------------------------------------------------------
// Pass 0a: split W into bf16 hi/lo
// ---------------------------------------------------------------------------
__global__ void wsplit_kernel(const float* __restrict__ Wq,
                              const float* __restrict__ Wk,
                              const float* __restrict__ Wv)
{
    const int o = blockIdx.x, mat = blockIdx.y, t = threadIdx.x;
    const float* W = (mat == 0) ? Wq : (mat == 1) ? Wk : Wv;
    float4 w = *(const float4*)(W + o * KDIM + t * 4);
    uint32_t h0, l0, h1, l1;
    split2(w.x, w.y, h0, l0);
    split2(w.z, w.w, h1, l1);
    *(uint2*)&gWh[mat][o][t * 4] = make_uint2(h0, h1);
    *(uint2*)&gWl[mat][o][t * 4] = make_uint2(l0, l1);
}

// ---------------------------------------------------------------------------
// Pass 0b: im2col + split
// ---------------------------------------------------------------------------
__global__ void im2col_kernel(const float* __restrict__ x)
{
    const int pw = threadIdx.x & 63;
    const int ph = blockIdx.x * 4 + (threadIdx.x >> 6);
    const int c = blockIdx.y, b = blockIdx.z;
    const float* xp = x + (((size_t)(b * CIN + c) * HIN + ph * 4) * WIN + pw * 4);
    uint32_t h[8], l[8];
    #pragma unroll
    for (int kh = 0; kh < 4; ++kh) {
        float4 v = *(const float4*)(xp + kh * WIN);
        split2(v.x, v.y, h[kh * 2], l[kh * 2]);
        split2(v.z, v.w, h[kh * 2 + 1], l[kh * 2 + 1]);
    }
    const int n = ph * 64 + pw;
    *(uint4*)&gAh[b][n][c * 16]     = make_uint4(h[0], h[1], h[2], h[3]);
    *(uint4*)&gAh[b][n][c * 16 + 8] = make_uint4(h[4], h[5], h[6], h[7]);
    *(uint4*)&gAl[b][n][c * 16]     = make_uint4(l[0], l[1], l[2], l[3]);
    *(uint4*)&gAl[b][n][c * 16 + 8] = make_uint4(l[4], l[5], l[6], l[7]);
}

// ---------------------------------------------------------------------------
// Pass 1: QKV GEMM via mma.sync bf16x3. Persistent grid (148), 3-stage ring.
// ---------------------------------------------------------------------------
#define GP 144
#define GTILE (128 * GP)
#define GSTAGE (4 * GTILE)
#define NITEMS (32 * BATCH * 3)

__device__ __forceinline__ void gchunk_async(uint32_t sbase,
                                             const __nv_bfloat16* __restrict__ gA_h,
                                             const __nv_bfloat16* __restrict__ gA_l,
                                             const __nv_bfloat16* __restrict__ gW_h,
                                             const __nv_bfloat16* __restrict__ gW_l,
                                             int kc0, int t)
{
    #pragma unroll
    for (int i = 0; i < 4; ++i) {
        int idx = t + i * 256;
        int row = idx >> 3, cs = idx & 7;
        uint32_t d = sbase + row * GP + cs * 16;
        size_t s = (size_t)row * KDIM + kc0 + cs * 8;
        cpasync16(d,              gA_h + s);
        cpasync16(d + GTILE,      gA_l + s);
        cpasync16(d + 2 * GTILE,  gW_h + s);
        cpasync16(d + 3 * GTILE,  gW_l + s);
    }
}

__global__ __launch_bounds__(256, 1) void qkv_mma_kernel(
    const float* __restrict__ bq, const float* __restrict__ bk,
    const float* __restrict__ bv)
{
    extern __shared__ __align__(128) char sb[];
    const uint32_t s0 = smem_u32(sb);
    const int t = threadIdx.x, lane = t & 31, wid = t >> 5;
    const int n0 = wid * 16;

    const uint32_t offA = (uint32_t)(n0 + (lane & 15)) * GP + (lane >> 4) * 16;
    const uint32_t offB = (uint32_t)((lane & 7) + ((lane >> 4) & 1) * 8) * GP +
                          ((lane >> 3) & 1) * 16;

    for (int item = blockIdx.x; item < NITEMS; item += gridDim.x) {
        const int nt = item & 31, b = (item >> 5) & 3, mat = item >> 7;
        const __nv_bfloat16* pAh = &gAh[b][nt * 128][0];
        const __nv_bfloat16* pAl = &gAl[b][nt * 128][0];
        const __nv_bfloat16* pWh = &gWh[mat][0][0];
        const __nv_bfloat16* pWl = &gWl[mat][0][0];
        const float* bias = (mat == 0) ? bq : (mat == 1) ? bk : bv;

        __syncthreads();
        gchunk_async(s0,          pAh, pAl, pWh, pWl, 0, t);
        CP_COMMIT();
        gchunk_async(s0 + GSTAGE, pAh, pAl, pWh, pWl, 64, t);
        CP_COMMIT();

        float S[16][4];
        #pragma unroll
        for (int j = 0; j < 16; ++j)
            #pragma unroll
            for (int c = 0; c < 4; ++c) S[j][c] = 0.0f;

        #pragma unroll 1
        for (int ch = 0; ch < 16; ++ch) {
            if (ch < 15) { CP_WAIT1(); } else { CP_WAIT0(); }
            __syncthreads();
            if (ch < 14) {
                gchunk_async(s0 + ((ch + 2) % 3) * GSTAGE, pAh, pAl, pWh, pWl, (ch + 2) * 64, t);
                CP_COMMIT();
            }
            const uint32_t st = s0 + (ch % 3) * GSTAGE;
            const uint32_t aA = st, aAl = st + GTILE, aW = st + 2 * GTILE, aWl = st + 3 * GTILE;

            #pragma unroll
            for (int kc = 0; kc < 4; ++kc) {
                uint32_t ah[4], al[4];
                ldsm4(ah, aA + offA + kc * 32);
                ldsm4(al, aAl + offA + kc * 32);
                #pragma unroll
                for (int h = 0; h < 2; ++h) {
                    uint32_t bh[4][4], bl[4][4];
                    #pragma unroll
                    for (int g = 0; g < 4; ++g) {
                        uint32_t ro = (uint32_t)(h * 4 + g) * 16 * GP + offB + kc * 32;
                        ldsm4(bh[g], aW + ro);
                        ldsm4(bl[g], aWl + ro);
                    }
                    #pragma unroll
                    for (int g = 0; g < 4; ++g) {
                        int og = h * 4 + g;
                        mma_bf16(S[2 * og],     ah, bh[g][0], bh[g][1]);
                        mma_bf16(S[2 * og + 1], ah, bh[g][2], bh[g][3]);
                    }
                    #pragma unroll
                    for (int g = 0; g < 4; ++g) {
                        int og = h * 4 + g;
                        mma_bf16(S[2 * og],     ah, bl[g][0], bl[g][1]);
                        mma_bf16(S[2 * og + 1], ah, bl[g][2], bl[g][3]);
                    }
                    #pragma unroll
                    for (int g = 0; g < 4; ++g) {
                        int og = h * 4 + g;
                        mma_bf16(S[2 * og],     al, bh[g][0], bh[g][1]);
                        mma_bf16(S[2 * og + 1], al, bh[g][2], bh[g][3]);
                    }
                }
            }
        }

        __nv_bfloat16* outh = (mat == 0) ? &gQh[b][0][0] : (mat == 1) ? &gKh[b][0][0] : &gVh[b][0][0];
        __nv_bfloat16* outl = (mat == 0) ? &gQl[b][0][0] : (mat == 1) ? &gKl[b][0][0] : &gVl[b][0][0];
        const int na = nt * 128 + n0 + (lane >> 2);
        #pragma unroll
        for (int j = 0; j < 16; ++j) {
            int o = j * 8 + (lane & 3) * 2;
            float b0 = bias[o], b1 = bias[o + 1];
            uint32_t h, l;
            split2(S[j][0] + b0, S[j][1] + b1, h, l);
            *(uint32_t*)(outh + (size_t)na * COUT + o) = h;
            *(uint32_t*)(outl + (size_t)na * COUT + o) = l;
            split2(S[j][2] + b0, S[j][3] + b1, h, l);
            *(uint32_t*)(outh + (size_t)(na + 8) * COUT + o) = h;
            *(uint32_t*)(outl + (size_t)(na + 8) * COUT + o) = l;
        }
    }
}

// ---------------------------------------------------------------------------
// Phase 2: FlashAttention-2, occupancy-optimized:
//  - CTA = 64 queries, 128 threads (4 warps), grid (64, BATCH) = 256 CTAs
//  - Q fragments resident in registers (loaded once via staging ldmatrix;
//    Q_hi staged at [0, 2*KTB), Q_lo at [2*KTB, 4*KTB) -- NO overlap)
//  - 32-key tiles, double-buffered K/V -> ~70 KB smem -> 2 CTAs/SM
// ---------------------------------------------------------------------------
#define TPITCH 272
#define KROWS  32
#define KTB    (KROWS * TPITCH)     // 8704
#define KVSTG  (4 * KTB)            // 34816 (Kh,Kl,Vh,Vl)
#define ATTN_SMEM (2 * KVSTG + 256) // ~70 KB

__device__ __forceinline__ void kv_async(uint32_t sbase,
                                         const __nv_bfloat16* __restrict__ pKh,
                                         const __nv_bfloat16* __restrict__ pKl,
                                         const __nv_bfloat16* __restrict__ pVh,
                                         const __nv_bfloat16* __restrict__ pVl,
                                         size_t goff, int t)
{
    #pragma unroll
    for (int i = 0; i < 4; ++i) {
        int idx = t + i * 128;          // 512 = 32 rows x 16 chunks
        int row = idx >> 4, c = idx & 15;
        uint32_t d = sbase + row * TPITCH + c * 16;
        size_t s = goff + (size_t)row * 128 + c * 8;
        cpasync16(d,           pKh + s);
        cpasync16(d + KTB,     pKl + s);
        cpasync16(d + 2 * KTB, pVh + s);
        cpasync16(d + 3 * KTB, pVl + s);
    }
}

__global__ __launch_bounds__(128, 2) void attn_kernel(float* __restrict__ out)
{
    extern __shared__ __align__(128) char sb[];
    const uint32_t aKV = smem_u32(sb);

    const int qt = blockIdx.x, b = blockIdx.y;
    const int t = threadIdx.x, lane = t & 31, wid = t >> 5;   // 4 warps
    const int n0 = wid * 16;

    const __nv_bfloat16* pKh = &gKh[b][0][0];
    const __nv_bfloat16* pKl = &gKl[b][0][0];
    const __nv_bfloat16* pVh = &gVh[b][0][0];
    const __nv_bfloat16* pVl = &gVl[b][0][0];

    const uint32_t offA = (uint32_t)(n0 + (lane & 15)) * TPITCH + (lane >> 4) * 16;
    const uint32_t offB_row = (uint32_t)((lane & 7) + ((lane >> 4) & 1) * 8) * TPITCH +
                              ((lane >> 3) & 1) * 16;
    const uint32_t offV_row = (uint32_t)((lane & 7) + ((lane >> 3) & 1) * 8) * TPITCH +
                              (lane >> 4) * 16;

    // ---- stage Q (64 rows x 128 bf16, hi+lo) into smem, ldsm to registers ----
    // Q_hi occupies [0, 2*KTB) (64 rows * TPITCH); Q_lo at [2*KTB, 4*KTB).
    {
        const __nv_bfloat16* gq = &gQh[b][qt * 64][0];
        const __nv_bfloat16* gl = &gQl[b][qt * 64][0];
        #pragma unroll
        for (int i = 0; i < 8; ++i) {
            int idx = t + i * 128;      // 1024 = 64 rows x 16 chunks
            int row = idx >> 4, c = idx & 15;
            *(uint4*)(sb + row * TPITCH + c * 16) = *(const uint4*)(gq + (size_t)row * 128 + c * 8);
            *(uint4*)(sb + 2 * KTB + row * TPITCH + c * 16) = *(const uint4*)(gl + (size_t)row * 128 + c * 8);
        }
    }
    __syncthreads();
    uint32_t Qh_[8][4], Ql_[8][4];
    #pragma unroll
    for (int kc = 0; kc < 8; ++kc) {
        ldsm4(Qh_[kc], aKV + offA + kc * 32);
        ldsm4(Ql_[kc], aKV + 2 * KTB + offA + kc * 32);
    }
    __syncthreads();    // staging area free

    kv_async(aKV, pKh, pKl, pVh, pVl, 0, t);
    CP_COMMIT();

    float O[16][4];
    #pragma unroll
    for (int j = 0; j < 16; ++j)
        #pragma unroll
        for (int c = 0; c < 4; ++c) O[j][c] = 0.0f;
    float m0 = -1e30f, m1 = -1e30f, l0 = 0.0f, l1 = 0.0f;

    #pragma unroll 1
    for (int mt = 0; mt < 128; ++mt) {
        CP_WAIT0();
        __syncthreads();
        if (mt < 127) {
            kv_async(aKV + ((mt + 1) & 1) * KVSTG, pKh, pKl, pVh, pVl,
                     (size_t)(mt + 1) * KROWS * 128, t);
            CP_COMMIT();
        }
        const uint32_t kb  = aKV + (mt & 1) * KVSTG;
        const uint32_t aKh = kb, aKl = kb + KTB, aVh = kb + 2 * KTB, aVl = kb + 3 * KTB;

        // ---- S = Qh*Kh + Qh*Kl + Ql*Kh  (16q x 32k per warp) ----
        float S[4][4];
        #pragma unroll
        for (int j = 0; j < 4; ++j)
            #pragma unroll
            for (int c = 0; c < 4; ++c) S[j][c] = 0.0f;

        #pragma unroll
        for (int kc = 0; kc < 8; ++kc) {
            uint32_t bh[2][4], bl[2][4];
            #pragma unroll
            for (int g = 0; g < 2; ++g) {
                uint32_t ro = (uint32_t)g * 16 * TPITCH + offB_row + kc * 32;
                ldsm4(bh[g], aKh + ro);
                ldsm4(bl[g], aKl + ro);
            }
            #pragma unroll
            for (int g = 0; g < 2; ++g) {
                mma_bf16(S[2 * g],     Qh_[kc], bh[g][0], bh[g][1]);
                mma_bf16(S[2 * g + 1], Qh_[kc], bh[g][2], bh[g][3]);
            }
            #pragma unroll
            for (int g = 0; g < 2; ++g) {
                mma_bf16(S[2 * g],     Qh_[kc], bl[g][0], bl[g][1]);
                mma_bf16(S[2 * g + 1], Qh_[kc], bl[g][2], bl[g][3]);
            }
            #pragma unroll
            for (int g = 0; g < 2; ++g) {
                mma_bf16(S[2 * g],     Ql_[kc], bh[g][0], bh[g][1]);
                mma_bf16(S[2 * g + 1], Ql_[kc], bh[g][2], bh[g][3]);
            }
        }

        // ---- online softmax (registers only) ----
        {
            float mx0 = -1e30f, mx1 = -1e30f;
            #pragma unroll
            for (int j = 0; j < 4; ++j) {
                mx0 = fmaxf(mx0, fmaxf(S[j][0], S[j][1]));
                mx1 = fmaxf(mx1, fmaxf(S[j][2], S[j][3]));
            }
            mx0 = fmaxf(mx0, __shfl_xor_sync(0xffffffffu, mx0, 1));
            mx0 = fmaxf(mx0, __shfl_xor_sync(0xffffffffu, mx0, 2));
            mx1 = fmaxf(mx1, __shfl_xor_sync(0xffffffffu, mx1, 1));
            mx1 = fmaxf(mx1, __shfl_xor_sync(0xffffffffu, mx1, 2));
            float mn0 = fmaxf(m0, mx0), mn1 = fmaxf(m1, mx1);
            bool resc = (mn0 > m0) || (mn1 > m1);
            float a0 = __expf(m0 - mn0), a1 = __expf(m1 - mn1);
            m0 = mn0; m1 = mn1;
            float ls0 = 0.0f, ls1 = 0.0f;
            #pragma unroll
            for (int j = 0; j < 4; ++j) {
                S[j][0] = __expf(S[j][0] - mn0); ls0 += S[j][0];
                S[j][1] = __expf(S[j][1] - mn0); ls0 += S[j][1];
                S[j][2] = __expf(S[j][2] - mn1); ls1 += S[j][2];
                S[j][3] = __expf(S[j][3] - mn1); ls1 += S[j][3];
            }
            if (resc) {
                #pragma unroll
                for (int j = 0; j < 16; ++j) {
                    O[j][0] *= a0; O[j][1] *= a0; O[j][2] *= a1; O[j][3] *= a1;
                }
            }
            ls0 += __shfl_xor_sync(0xffffffffu, ls0, 1);
            ls0 += __shfl_xor_sync(0xffffffffu, ls0, 2);
            ls1 += __shfl_xor_sync(0xffffffffu, ls1, 1);
            ls1 += __shfl_xor_sync(0xffffffffu, ls1, 2);
            l0 = l0 * a0 + ls0;
            l1 = l1 * a1 + ls1;
        }

        // ---- O += Ph*Vh + Ph*Vl + Pl*Vh ----
        #pragma unroll
        for (int kc = 0; kc < 2; ++kc) {
            uint32_t ah[4], al[4];
            split2(S[2 * kc][0],     S[2 * kc][1],     ah[0], al[0]);
            split2(S[2 * kc][2],     S[2 * kc][3],     ah[1], al[1]);
            split2(S[2 * kc + 1][0], S[2 * kc + 1][1], ah[2], al[2]);
            split2(S[2 * kc + 1][2], S[2 * kc + 1][3], ah[3], al[3]);
            #pragma unroll
            for (int h = 0; h < 2; ++h) {
                uint32_t vh[4][4], vl[4][4];
                #pragma unroll
                for (int g = 0; g < 4; ++g) {
                    uint32_t ro = (uint32_t)kc * 16 * TPITCH + offV_row + (h * 4 + g) * 32;
                    ldsm4t(vh[g], aVh + ro);
                    ldsm4t(vl[g], aVl + ro);
                }
                #pragma unroll
                for (int g = 0; g < 4; ++g) {
                    int og = h * 4 + g;
                    mma_bf16(O[2 * og],     ah, vh[g][0], vh[g][1]);
                    mma_bf16(O[2 * og + 1], ah, vh[g][2], vh[g][3]);
                }
                #pragma unroll
                for (int g = 0; g < 4; ++g) {
                    int og = h * 4 + g;
                    mma_bf16(O[2 * og],     ah, vl[g][0], vl[g][1]);
                    mma_bf16(O[2 * og + 1], ah, vl[g][2], vl[g][3]);
                }
                #pragma unroll
                for (int g = 0; g < 4; ++g) {
                    int og = h * 4 + g;
                    mma_bf16(O[2 * og],     al, vh[g][0], vh[g][1]);
                    mma_bf16(O[2 * og + 1], al, vh[g][2], vh[g][3]);
                }
            }
        }
    }

    const float i0 = 1.0f / l0, i1 = 1.0f / l1;
    const int nbase = qt * 64 + n0 + (lane >> 2);
    #pragma unroll
    for (int j = 0; j < 16; ++j) {
        int o = j * 8 + (lane & 3) * 2;
        float* p0 = out + ((size_t)(b * COUT + o)) * NP + nbase;
        float* p1 = out + ((size_t)(b * COUT + o + 1)) * NP + nbase;
        p0[0] = O[j][0] * i0;
        p1[0] = O[j][1] * i0;
        p0[8] = O[j][2] * i1;
        p1[8] = O[j][3] * i1;
    }
}

// ---------------------------------------------------------------------------
extern "C" void kernel_launch(void* const* d_in, const int* in_sizes, int n_in,
                              void* d_out, int out_size)
{
    (void)in_sizes; (void)n_in; (void)out_size;
    const float* x  = (const float*)d_in[0];
    const float* Wq = (const float*)d_in[1];
    const float* bq = (const float*)d_in[2];
    const float* Wk = (const float*)d_in[3];
    const float* bk = (const float*)d_in[4];
    const float* Wv = (const float*)d_in[5];
    const float* bv = (const float*)d_in[6];
    float* out = (float*)d_out;

    cudaFuncSetAttribute(qkv_mma_kernel, cudaFuncAttributeMaxDynamicSharedMemorySize,
                         3 * GSTAGE);
    cudaFuncSetAttribute(attn_kernel, cudaFuncAttributeMaxDynamicSharedMemorySize,
                         ATTN_SMEM);

    wsplit_kernel<<<dim3(COUT, 3), 256>>>(Wq, Wk, Wv);
    im2col_kernel<<<dim3(16, CIN, BATCH), 256>>>(x);
    qkv_mma_kernel<<<148, 256, 3 * GSTAGE>>>(bq, bk, bv);
    attn_kernel<<<dim3(64, BATCH), 128, ATTN_SMEM>>>(out);
}